// round 1
// baseline (speedup 1.0000x reference)
#include <cuda_runtime.h>
#include <math.h>

#define NQ    12
#define DIM   4096
#define TT    8
#define BB    32
#define SHOTS 256
#define KMAX  96

// Final evolved states exp(-i t H)|init>, one complex vector per t.
__device__ float2 g_states[TT][DIM];

// ---------------------------------------------------------------------------
// Kernel B: Chebyshev time evolution. One block per t, state in shared memory.
//   H' = H / lambda, x = t*lambda
//   exp(-i x H') = sum_k (2-d_k0)(-i)^k J_k(x) T_k(H')
//   phi_{k+1} = 2 H' phi_k - phi_{k-1}, all phi real.
// ---------------------------------------------------------------------------
__global__ __launch_bounds__(512, 1)
void evolve_kernel(const int* __restrict__ d_init,
                   const float* __restrict__ d_ts,
                   const float* __restrict__ d_px,
                   const float* __restrict__ d_pzz)
{
    __shared__ float buf0[DIM];
    __shared__ float buf1[DIM];
    __shared__ float s_cr[KMAX + 1];
    __shared__ float s_ci[KMAX + 1];
    __shared__ int   s_K;

    const int tid = threadIdx.x;
    const int t   = blockIdx.x;

    // lambda = sum|x| + sum|zz|  (upper bound on spectral radius)
    float px[NQ];
    float lambda = 0.f;
#pragma unroll
    for (int i = 0; i < NQ; i++) { px[i] = d_px[i]; lambda += fabsf(px[i]); }
    float pzz[NQ - 1];
#pragma unroll
    for (int i = 0; i < NQ - 1; i++) { pzz[i] = d_pzz[i]; lambda += fabsf(pzz[i]); }
    if (lambda < 1e-20f) lambda = 1e-20f;
    const float inv_l = 1.0f / lambda;
#pragma unroll
    for (int i = 0; i < NQ; i++) px[i] *= inv_l;

    // per-owned-entry scaled diagonal (ZZ part)
    float diag[8];
#pragma unroll
    for (int e = 0; e < 8; e++) {
        const int s = tid + (e << 9);
        float d = 0.f;
#pragma unroll
        for (int i = 0; i < NQ - 1; i++) {
            const int bi = (s >> i) & 1;
            const int bj = (s >> (i + 1)) & 1;
            d += (bi == bj) ? pzz[i] : -pzz[i];
        }
        diag[e] = d * inv_l;
    }

    // Thread 0: Bessel coefficients J_k(x) via Miller downward recurrence (double).
    if (tid == 0) {
        double x = (double)d_ts[t] * (double)lambda;
        if (x < 1e-5) x = 1e-5;
        int K = (int)ceil(x) + 25;
        if (K > KMAX) K = KMAX;
        const int M = K + 14;
        double v[KMAX + 16];
        v[M] = 1e-30;
        const double inv_x = 1.0 / x;
        double up = 0.0;                 // v[M+1]
        for (int k = M; k >= 1; k--) {
            const double nv = (2.0 * (double)k * inv_x) * v[k] - up;
            up = v[k];
            v[k - 1] = nv;
        }
        double S = v[0];
        for (int m = 2; m <= M; m += 2) S += 2.0 * v[m];
        const double invS = 1.0 / S;
        for (int k = 0; k <= K; k++) {
            const double Jk = v[k] * invS;
            const double c  = (k == 0) ? Jk : 2.0 * Jk;
            float cr = 0.f, ci = 0.f;
            switch (k & 3) {             // (-i)^k
                case 0: cr = (float)c;  break;
                case 1: ci = (float)-c; break;
                case 2: cr = (float)-c; break;
                case 3: ci = (float)c;  break;
            }
            s_cr[k] = cr;
            s_ci[k] = ci;
        }
        s_K = K;
    }
    __syncthreads();

    const int K    = s_K;
    const int init = *d_init;

    float cur[8], prev[8], psr[8], psi[8];
#pragma unroll
    for (int e = 0; e < 8; e++) {
        const int s = tid + (e << 9);
        const float vv = (s == init) ? 1.f : 0.f;
        cur[e]  = vv;
        prev[e] = 0.f;
        buf0[s] = vv;
        psr[e]  = s_cr[0] * vv;
        psi[e]  = 0.f;
    }
    __syncthreads();

    for (int k = 1; k <= K; k++) {
        const float* __restrict__ src = (k & 1) ? buf0 : buf1;  // holds phi_{k-1}
        float* __restrict__       dst = (k & 1) ? buf1 : buf0;
        const float cr = s_cr[k];
        const float ci = s_ci[k];
        float nxt[8];
#pragma unroll
        for (int e = 0; e < 8; e++) {
            const int s = tid + (e << 9);
            float vv = diag[e] * cur[e];
            // high-bit flips (bits 9,10,11) live in this thread's registers
            vv = fmaf(px[9],  cur[e ^ 1], vv);
            vv = fmaf(px[10], cur[e ^ 2], vv);
            vv = fmaf(px[11], cur[e ^ 4], vv);
#pragma unroll
            for (int i = 0; i < 9; i++)
                vv = fmaf(px[i], src[s ^ (1 << i)], vv);
            nxt[e] = (k > 1) ? (2.f * vv - prev[e]) : vv;
        }
#pragma unroll
        for (int e = 0; e < 8; e++) {
            prev[e] = cur[e];
            cur[e]  = nxt[e];
            dst[tid + (e << 9)] = nxt[e];
            psr[e] = fmaf(cr, nxt[e], psr[e]);
            psi[e] = fmaf(ci, nxt[e], psi[e]);
        }
        __syncthreads();
    }

#pragma unroll
    for (int e = 0; e < 8; e++)
        g_states[t][tid + (e << 9)] = make_float2(psr[e], psi[e]);
}

// ---------------------------------------------------------------------------
// Kernel C: per-(t,b) basis rotation (butterflies, Z skipped) + gather probs.
// Pauli position i acts on bit (N-1-i) of the state index (row-major reshape).
// ---------------------------------------------------------------------------
__global__ __launch_bounds__(256)
void measure_kernel(const int* __restrict__ d_pauli,
                    const int* __restrict__ d_idx,
                    float* __restrict__ d_out)
{
    __shared__ float re[DIM];
    __shared__ float im[DIM];

    const int tid = threadIdx.x;
    const int b   = blockIdx.x;
    const int t   = blockIdx.y;

#pragma unroll
    for (int r = 0; r < DIM / 256; r++) {
        const int s = tid + (r << 8);
        const float2 v = g_states[t][s];
        re[s] = v.x;
        im[s] = v.y;
    }
    __syncthreads();

    const float inv_s2 = 0.70710678118654752f;

    for (int m = NQ - 1; m >= 0; m--) {
        const int p = d_pauli[b * NQ + (NQ - 1 - m)];
        if (p == 2) continue;            // Z: identity rotation
        const int lowmask = (1 << m) - 1;
#pragma unroll
        for (int r = 0; r < (DIM / 2) / 256; r++) {
            const int q  = tid + (r << 8);
            const int s0 = ((q & ~lowmask) << 1) | (q & lowmask);
            const int s1 = s0 | (1 << m);
            const float r0 = re[s0], i0 = im[s0];
            const float r1 = re[s1], i1 = im[s1];
            float nr0, ni0, nr1, ni1;
            if (p == 0) {                // X basis: H gate
                nr0 = r0 + r1;  ni0 = i0 + i1;
                nr1 = r0 - r1;  ni1 = i0 - i1;
            } else {                     // Y basis: [[1,-i],[1,i]]/sqrt2
                nr0 = r0 + i1;  ni0 = i0 - r1;
                nr1 = r0 - i1;  ni1 = i0 + r1;
            }
            re[s0] = nr0 * inv_s2;  im[s0] = ni0 * inv_s2;
            re[s1] = nr1 * inv_s2;  im[s1] = ni1 * inv_s2;
        }
        __syncthreads();
    }

    const int base = (t * BB + b) * SHOTS;
    const int idx  = d_idx[base + tid];
    const float pr = re[idx];
    const float pi = im[idx];
    d_out[base + tid] = pr * pr + pi * pi;
}

// ---------------------------------------------------------------------------
extern "C" void kernel_launch(void* const* d_in, const int* in_sizes, int n_in,
                              void* d_out, int out_size)
{
    const int*   d_init  = (const int*)  d_in[0];
    const float* d_ts    = (const float*)d_in[1];
    const int*   d_pauli = (const int*)  d_in[2];
    const int*   d_idx   = (const int*)  d_in[3];
    const float* d_px    = (const float*)d_in[4];
    const float* d_pzz   = (const float*)d_in[5];

    evolve_kernel<<<TT, 512>>>(d_init, d_ts, d_px, d_pzz);
    measure_kernel<<<dim3(BB, TT), 256>>>(d_pauli, d_idx, (float*)d_out);
}